// round 13
// baseline (speedup 1.0000x reference)
#include <cuda_runtime.h>
#include <cuda_bf16.h>
#include <cstdint>

#define VOCAB  32000
#define HIDDEN 4096
#define NTOK   4096      // 8*512 tokens
#define SEQ    512
#define NP     250       // VOCAB / 128 partial tiles per row
#define IGNORE_INDEX (-100)

#define BK     32                // bf16 per K block
#define NKB    (HIDDEN / BK)     // 128
#define NSTAGE 4
#define ROWB   80                // padded row stride in bytes (40 bf16)
#define ABYTES (256 * ROWB)      // 20480 : A = 256 rows per stage
#define BBYTES (128 * ROWB)      // 10240 : B = 128 rows per stage
#define STAGEB (ABYTES + BBYTES) // 30720
#define OFF_RED (NSTAGE * STAGEB)            // 122880
#define SMEM_BYTES (OFF_RED + 256 * 2 * 8)   // + red[256][2] float2 = 126976

// ---------------- scratch (device globals; no allocation allowed) ----------
__device__ __align__(128) __nv_bfloat16 g_W[(size_t)VOCAB * HIDDEN];  // 262 MB
__device__ __align__(128) __nv_bfloat16 g_X[(size_t)NTOK * HIDDEN];   // 33 MB
__device__ float g_pmax[(size_t)NTOK * NP];
__device__ float g_psum[(size_t)NTOK * NP];
__device__ float g_tgt[NTOK];
__device__ float g_ptok[NTOK];

// ---------------- small asm helpers ----------------------------------------
__device__ __forceinline__ uint32_t smem_u32(const void* p) {
    uint32_t a;
    asm("{ .reg .u64 t; cvta.to.shared.u64 t, %1; cvt.u32.u64 %0, t; }"
        : "=r"(a) : "l"(p));
    return a;
}
#define CP_ASYNC16(dst, src) \
    asm volatile("cp.async.cg.shared.global [%0], [%1], 16;" :: "r"(dst), "l"(src))
#define CP_COMMIT() asm volatile("cp.async.commit_group;" ::: "memory")
#define CP_WAIT(n)  asm volatile("cp.async.wait_group %0;" :: "n"(n) : "memory")

#define LDMATRIX_X4(r0, r1, r2, r3, addr) \
    asm volatile("ldmatrix.sync.aligned.m8n8.x4.shared.b16 {%0,%1,%2,%3}, [%4];" \
                 : "=r"(r0), "=r"(r1), "=r"(r2), "=r"(r3) : "r"(addr))

__device__ __forceinline__ void mma16816(float c[4],
                                         uint32_t a0, uint32_t a1, uint32_t a2, uint32_t a3,
                                         uint32_t b0, uint32_t b1) {
    asm volatile(
        "mma.sync.aligned.m16n8k16.row.col.f32.bf16.bf16.f32 "
        "{%0,%1,%2,%3}, {%4,%5,%6,%7}, {%8,%9}, {%0,%1,%2,%3};\n"
        : "+f"(c[0]), "+f"(c[1]), "+f"(c[2]), "+f"(c[3])
        : "r"(a0), "r"(a1), "r"(a2), "r"(a3), "r"(b0), "r"(b1));
}

// ---------------- fp32 -> bf16 conversion ----------------------------------
__global__ void conv_kernel(const float4* __restrict__ src,
                            __nv_bfloat162* __restrict__ dst, int n4) {
    for (int i = blockIdx.x * blockDim.x + threadIdx.x; i < n4;
         i += gridDim.x * blockDim.x) {
        float4 v = src[i];
        dst[2 * i]     = __floats2bfloat162_rn(v.x, v.y);
        dst[2 * i + 1] = __floats2bfloat162_rn(v.z, v.w);
    }
}

// ---------------- exact fp32 target logits ----------------------------------
__global__ void tgt_kernel(const float* __restrict__ x,
                           const float* __restrict__ w,
                           const float* __restrict__ bias,
                           const int* __restrict__ target) {
    const int row  = blockIdx.x * 8 + (threadIdx.x >> 5);
    const int lane = threadIdx.x & 31;
    const int t = target[row];
    if (t == IGNORE_INDEX) {
        if (lane == 0) g_tgt[row] = 0.f;
        return;
    }
    const float4* xr = reinterpret_cast<const float4*>(x + (size_t)row * HIDDEN);
    const float4* wr = reinterpret_cast<const float4*>(w + (size_t)t * HIDDEN);
    float s = 0.f;
#pragma unroll 4
    for (int j = lane; j < HIDDEN / 4; j += 32) {
        float4 a = xr[j];
        float4 b = wr[j];
        s += a.x * b.x + a.y * b.y + a.z * b.z + a.w * b.w;
    }
#pragma unroll
    for (int off = 16; off; off >>= 1)
        s += __shfl_xor_sync(0xffffffffu, s, off);
    if (lane == 0) g_tgt[row] = s + bias[t];
}

// ---------------- stage loader: cp.async GMEM bf16 -> padded SMEM -----------
// 256 threads: A 1024 chunks (256 rows x 4), B 512 chunks -> 6 per thread.
__device__ __forceinline__ void load_stage(uint32_t sb, int stage, int kb,
                                           int m0, int n0, int tid) {
    const uint32_t base = sb + stage * STAGEB;
#pragma unroll
    for (int h = 0; h < 4; h++) {           // A: 256 rows
        const int c   = tid + h * 256;
        const int row = c >> 2;
        const int seg = c & 3;
        const uint32_t dA = base + row * ROWB + seg * 16;
        const __nv_bfloat16* sA = g_X + (size_t)(m0 + row) * HIDDEN + kb * BK + seg * 8;
        CP_ASYNC16(dA, sA);
    }
#pragma unroll
    for (int h = 0; h < 2; h++) {           // B: 128 rows
        const int c   = tid + h * 256;
        const int row = c >> 2;
        const int seg = c & 3;
        const uint32_t dB = base + ABYTES + row * ROWB + seg * 16;
        const __nv_bfloat16* sB = g_W + (size_t)(n0 + row) * HIDDEN + kb * BK + seg * 8;
        CP_ASYNC16(dB, sB);
    }
}

// ---------------- bf16 GEMM (ldmatrix + mma.16816) + fused LSE --------------
// Grid (16 m-tiles [fast], 250 n-tiles). 256 threads, 8 warps (4x2).
// CTA tile 256x128, warp tile 64x64, BK=32, 4-stage cp.async pipeline.
__global__ __launch_bounds__(256, 1)
void gemm_lse_kernel(const float* __restrict__ bias) {
    extern __shared__ char smem[];
    const uint32_t sb = smem_u32(smem);

    const int tid  = threadIdx.x;
    const int lane = tid & 31;
    const int warp = tid >> 5;
    const int g    = lane >> 2;     // 0..7
    const int tig  = lane & 3;      // 0..3
    const int wm   = warp >> 1;     // 0..3 : rows wm*64..+63
    const int wn   = warp & 1;      // 0..1 : cols wn*64..+63
    const int m0   = blockIdx.x * 256;
    const int n0   = blockIdx.y * 128;

    float acc[4][8][4];
#pragma unroll
    for (int i = 0; i < 4; i++)
#pragma unroll
        for (int j = 0; j < 8; j++)
#pragma unroll
            for (int k = 0; k < 4; k++) acc[i][j][k] = 0.f;

    // prologue: 3 stages in flight
    load_stage(sb, 0, 0, m0, n0, tid); CP_COMMIT();
    load_stage(sb, 1, 1, m0, n0, tid); CP_COMMIT();
    load_stage(sb, 2, 2, m0, n0, tid); CP_COMMIT();

    // ldmatrix lane addressing (constant across stages)
    const int a_row  = lane & 15;
    const int a_col8 = (lane >> 4) & 1;            // +8 bf16 col
    const int b_n    = ((lane >> 4) & 1) * 8 + (lane & 7);
    const int b_k8   = (lane >> 3) & 1;            // +8 bf16 col
    uint32_t offA[4], offB[4];
#pragma unroll
    for (int mt = 0; mt < 4; mt++)
        offA[mt] = (wm * 64 + mt * 16 + a_row) * ROWB + a_col8 * 16;
#pragma unroll
    for (int np = 0; np < 4; np++)
        offB[np] = ABYTES + (wn * 64 + np * 16 + b_n) * ROWB + b_k8 * 16;

    for (int kb = 0; kb < NKB; kb++) {
        const int rem = NKB - 1 - kb;
        if (rem >= 2)      CP_WAIT(2);
        else if (rem == 1) CP_WAIT(1);
        else               CP_WAIT(0);
        __syncthreads();

        if (kb + 3 < NKB) {
            load_stage(sb, (kb + 3) & 3, kb + 3, m0, n0, tid);
            CP_COMMIT();
        }

        const uint32_t base = sb + (kb & 3) * STAGEB;
#pragma unroll
        for (int kh = 0; kh < 2; kh++) {
            const uint32_t hb = base + kh * 32;
            uint32_t a[4][4], b[8][2];
#pragma unroll
            for (int mt = 0; mt < 4; mt++)
                LDMATRIX_X4(a[mt][0], a[mt][1], a[mt][2], a[mt][3],
                            hb + offA[mt]);
#pragma unroll
            for (int np = 0; np < 4; np++) {
                uint32_t r0, r1, r2, r3;
                LDMATRIX_X4(r0, r1, r2, r3, hb + offB[np]);
                b[np * 2][0] = r0;     b[np * 2][1] = r1;
                b[np * 2 + 1][0] = r2; b[np * 2 + 1][1] = r3;
            }
#pragma unroll
            for (int mt = 0; mt < 4; mt++)
#pragma unroll
                for (int nt = 0; nt < 8; nt++)
                    mma16816(acc[mt][nt], a[mt][0], a[mt][1], a[mt][2], a[mt][3],
                             b[nt][0], b[nt][1]);
        }
    }
    __syncthreads();   // SMEM now reusable for reduction

    // --------- fused epilogue: bias + row (max, sumexp) partials ------------
    float2 (*red)[2] = (float2(*)[2])(smem + OFF_RED);
#pragma unroll
    for (int mt = 0; mt < 4; mt++) {
#pragma unroll
        for (int half = 0; half < 2; half++) {
            const int rloc = wm * 64 + mt * 16 + g + half * 8;
            float v[16];
            float vmax = -1e30f;
#pragma unroll
            for (int nt = 0; nt < 8; nt++) {
                const int c0g = n0 + wn * 64 + nt * 8 + tig * 2;
                float v0 = acc[mt][nt][half * 2 + 0] + bias[c0g];
                float v1 = acc[mt][nt][half * 2 + 1] + bias[c0g + 1];
                v[nt * 2]     = v0;
                v[nt * 2 + 1] = v1;
                vmax = fmaxf(vmax, fmaxf(v0, v1));
            }
            float vsum = 0.f;
#pragma unroll
            for (int j = 0; j < 16; j++) vsum += __expf(v[j] - vmax);
#pragma unroll
            for (int off = 1; off < 4; off <<= 1) {
                float om = __shfl_xor_sync(0xffffffffu, vmax, off);
                float os = __shfl_xor_sync(0xffffffffu, vsum, off);
                float nm = fmaxf(vmax, om);
                vsum = vsum * __expf(vmax - nm) + os * __expf(om - nm);
                vmax = nm;
            }
            if (tig == 0) red[rloc][wn] = make_float2(vmax, vsum);
        }
    }
    __syncthreads();
    {
        float m = -1e30f, s = 0.f;
#pragma unroll
        for (int w = 0; w < 2; w++) {
            float2 p = red[tid][w];
            float nm = fmaxf(m, p.x);
            s = s * __expf(m - nm) + p.y * __expf(p.x - nm);
            m = nm;
        }
        const size_t idx = (size_t)(m0 + tid) * NP + blockIdx.y;
        g_pmax[idx] = m;
        g_psum[idx] = s;
    }
}

// ---------------- combine partials -> per-token logp ------------------------
__global__ void lse_kernel(const int* __restrict__ target) {
    const int row  = blockIdx.x * 8 + (threadIdx.x >> 5);
    const int lane = threadIdx.x & 31;
    const float* pm = g_pmax + (size_t)row * NP;
    const float* ps = g_psum + (size_t)row * NP;
    float m = -1e30f, s = 0.f;
    for (int j = lane; j < NP; j += 32) {
        float om = pm[j], os = ps[j];
        float nm = fmaxf(m, om);
        s = s * __expf(m - nm) + os * __expf(om - nm);
        m = nm;
    }
#pragma unroll
    for (int off = 16; off; off >>= 1) {
        float om = __shfl_xor_sync(0xffffffffu, m, off);
        float os = __shfl_xor_sync(0xffffffffu, s, off);
        float nm = fmaxf(m, om);
        s = s * __expf(m - nm) + os * __expf(om - nm);
        m = nm;
    }
    if (lane == 0) {
        const float lse = m + logf(s);
        const int t = target[row];
        g_ptok[row] = (t != IGNORE_INDEX) ? (g_tgt[row] - lse) : 0.f;
    }
}

// ---------------- final scalar loss -----------------------------------------
__global__ void final_kernel(const int* __restrict__ target,
                             const float* __restrict__ ref_c,
                             const float* __restrict__ ref_r,
                             float* __restrict__ out) {
    __shared__ float ssum[8];
    __shared__ float scnt[8];
    const int warp = threadIdx.x >> 5;
    const int lane = threadIdx.x & 31;
    float s = 0.f, c = 0.f;
    for (int t = lane; t < SEQ; t += 32) {
        const int row = warp * SEQ + t;
        if (target[row] != IGNORE_INDEX) {
            s += g_ptok[row];
            c += 1.f;
        }
    }
#pragma unroll
    for (int off = 16; off; off >>= 1) {
        s += __shfl_xor_sync(0xffffffffu, s, off);
        c += __shfl_xor_sync(0xffffffffu, c, off);
    }
    if (lane == 0) { ssum[warp] = s; scnt[warp] = c; }
    __syncthreads();
    if (threadIdx.x == 0) {
        float nll_num = 0.f, nll_den = 0.f;
        for (int b = 0; b < 4; b++) { nll_num += ssum[b]; nll_den += scnt[b]; }
        const float nll = -nll_num / nll_den;
        float pl = 0.f;
        for (int i = 0; i < 4; i++) {
            const float ca = ssum[i] / scnt[i] - ref_c[i];
            const float ra = ssum[4 + i] / scnt[4 + i] - ref_r[i];
            const float x  = 0.1f * (ca - ra);
            const float ls = fminf(x, 0.f) - log1pf(expf(-fabsf(x)));
            pl -= ls;
        }
        pl *= 0.25f;
        out[0] = pl + nll;
    }
}

// ---------------- launcher ---------------------------------------------------
extern "C" void kernel_launch(void* const* d_in, const int* in_sizes, int n_in,
                              void* d_out, int out_size) {
    const float* lin_w = (const float*)d_in[0];
    const float* x     = (const float*)d_in[1];
    const int*   tgt   = (const int*)d_in[2];
    const float* ref_c = (const float*)d_in[3];
    const float* ref_r = (const float*)d_in[4];
    const float* bias  = (const float*)d_in[5];
    float* out = (float*)d_out;

    cudaFuncSetAttribute(gemm_lse_kernel,
                         cudaFuncAttributeMaxDynamicSharedMemorySize, SMEM_BYTES);

    __nv_bfloat162* dW;
    __nv_bfloat162* dX;
    cudaGetSymbolAddress((void**)&dW, g_W);
    cudaGetSymbolAddress((void**)&dX, g_X);

    conv_kernel<<<2048, 256>>>((const float4*)lin_w, dW, VOCAB * HIDDEN / 4);
    conv_kernel<<<512, 256>>>((const float4*)x, dX, NTOK * HIDDEN / 4);

    tgt_kernel<<<NTOK / 8, 256>>>(x, lin_w, bias, tgt);

    dim3 grid(NTOK / 256, NP);   // m fast-varying -> B panel shared in-wave
    gemm_lse_kernel<<<grid, 256, SMEM_BYTES>>>(bias);

    lse_kernel<<<NTOK / 8, 256>>>(tgt);
    final_kernel<<<1, 256>>>(tgt, ref_c, ref_r, out);
}

// round 14
// speedup vs baseline: 1.4166x; 1.4166x over previous
#include <cuda_runtime.h>
#include <cuda_bf16.h>
#include <cstdint>

#define VOCAB  32000
#define HIDDEN 4096
#define NTOK   4096      // 8*512 tokens
#define SEQ    512
#define NP     250       // VOCAB / 128 partial tiles per row
#define IGNORE_INDEX (-100)

#define BK     32                // bf16 per K block
#define NKB    (HIDDEN / BK)     // 128
#define NSTAGE 4
#define ROWB   80                // padded row stride in bytes (40 bf16)
#define ABYTES (128 * ROWB)      // 10240 per operand per stage
#define STAGEB (2 * ABYTES)      // 20480 (A then B)
#define OFF_RED (NSTAGE * STAGEB)            // 81920
#define SMEM_BYTES (OFF_RED + 128 * 2 * 8)   // + red[128][2] float2 = 83968

// ---------------- scratch (device globals; no allocation allowed) ----------
__device__ __align__(128) __nv_bfloat16 g_W[(size_t)VOCAB * HIDDEN];  // 262 MB
__device__ __align__(128) __nv_bfloat16 g_X[(size_t)NTOK * HIDDEN];   // 33 MB
__device__ float g_pmax[(size_t)NTOK * NP];
__device__ float g_psum[(size_t)NTOK * NP];
__device__ float g_tgt[NTOK];
__device__ float g_ptok[NTOK];

// ---------------- small asm helpers ----------------------------------------
__device__ __forceinline__ uint32_t smem_u32(const void* p) {
    uint32_t a;
    asm("{ .reg .u64 t; cvta.to.shared.u64 t, %1; cvt.u32.u64 %0, t; }"
        : "=r"(a) : "l"(p));
    return a;
}
#define CP_ASYNC16(dst, src) \
    asm volatile("cp.async.cg.shared.global [%0], [%1], 16;" :: "r"(dst), "l"(src))
#define CP_COMMIT() asm volatile("cp.async.commit_group;" ::: "memory")
#define CP_WAIT(n)  asm volatile("cp.async.wait_group %0;" :: "n"(n) : "memory")

#define LDMATRIX_X4(r0, r1, r2, r3, addr) \
    asm volatile("ldmatrix.sync.aligned.m8n8.x4.shared.b16 {%0,%1,%2,%3}, [%4];" \
                 : "=r"(r0), "=r"(r1), "=r"(r2), "=r"(r3) : "r"(addr))

__device__ __forceinline__ void mma16816(float c[4],
                                         uint32_t a0, uint32_t a1, uint32_t a2, uint32_t a3,
                                         uint32_t b0, uint32_t b1) {
    asm volatile(
        "mma.sync.aligned.m16n8k16.row.col.f32.bf16.bf16.f32 "
        "{%0,%1,%2,%3}, {%4,%5,%6,%7}, {%8,%9}, {%0,%1,%2,%3};\n"
        : "+f"(c[0]), "+f"(c[1]), "+f"(c[2]), "+f"(c[3])
        : "r"(a0), "r"(a1), "r"(a2), "r"(a3), "r"(b0), "r"(b1));
}

// ---------------- fp32 -> bf16 conversion ----------------------------------
__global__ void conv_kernel(const float4* __restrict__ src,
                            __nv_bfloat162* __restrict__ dst, int n4) {
    for (int i = blockIdx.x * blockDim.x + threadIdx.x; i < n4;
         i += gridDim.x * blockDim.x) {
        float4 v = src[i];
        dst[2 * i]     = __floats2bfloat162_rn(v.x, v.y);
        dst[2 * i + 1] = __floats2bfloat162_rn(v.z, v.w);
    }
}

// ---------------- exact fp32 target logits ----------------------------------
__global__ void tgt_kernel(const float* __restrict__ x,
                           const float* __restrict__ w,
                           const float* __restrict__ bias,
                           const int* __restrict__ target) {
    const int row  = blockIdx.x * 8 + (threadIdx.x >> 5);
    const int lane = threadIdx.x & 31;
    const int t = target[row];
    if (t == IGNORE_INDEX) {
        if (lane == 0) g_tgt[row] = 0.f;
        return;
    }
    const float4* xr = reinterpret_cast<const float4*>(x + (size_t)row * HIDDEN);
    const float4* wr = reinterpret_cast<const float4*>(w + (size_t)t * HIDDEN);
    float s = 0.f;
#pragma unroll 4
    for (int j = lane; j < HIDDEN / 4; j += 32) {
        float4 a = xr[j];
        float4 b = wr[j];
        s += a.x * b.x + a.y * b.y + a.z * b.z + a.w * b.w;
    }
#pragma unroll
    for (int off = 16; off; off >>= 1)
        s += __shfl_xor_sync(0xffffffffu, s, off);
    if (lane == 0) g_tgt[row] = s + bias[t];
}

// ---------------- stage loader: cp.async GMEM bf16 -> padded SMEM -----------
// 128 threads: 512 16B chunks per operand per stage -> 4 per thread each.
__device__ __forceinline__ void load_stage(uint32_t sb, int stage, int kb,
                                           int m0, int n0, int tid) {
    const uint32_t base = sb + stage * STAGEB;
#pragma unroll
    for (int h = 0; h < 4; h++) {
        const int c   = tid + h * 128;
        const int row = c >> 2;
        const int seg = c & 3;
        const uint32_t dA = base + row * ROWB + seg * 16;
        const __nv_bfloat16* sA = g_X + (size_t)(m0 + row) * HIDDEN + kb * BK + seg * 8;
        CP_ASYNC16(dA, sA);
        const uint32_t dB = base + ABYTES + row * ROWB + seg * 16;
        const __nv_bfloat16* sB = g_W + (size_t)(n0 + row) * HIDDEN + kb * BK + seg * 8;
        CP_ASYNC16(dB, sB);
    }
}

// ---------------- bf16 GEMM (ldmatrix + mma.16816) + fused LSE --------------
// Grid (32 m-tiles [fast], 250 n-tiles). 128 threads, 4 warps (2x2).
// CTA tile 128x128, warp tile 64x64, BK=32, 4-stage cp.async pipeline.
__global__ __launch_bounds__(128, 2)
void gemm_lse_kernel(const float* __restrict__ bias) {
    extern __shared__ char smem[];
    const uint32_t sb = smem_u32(smem);

    const int tid  = threadIdx.x;
    const int lane = tid & 31;
    const int warp = tid >> 5;
    const int g    = lane >> 2;     // 0..7
    const int tig  = lane & 3;      // 0..3
    const int wm   = warp >> 1;     // 0..1 : rows wm*64..+63
    const int wn   = warp & 1;      // 0..1 : cols wn*64..+63
    const int m0   = blockIdx.x * 128;
    const int n0   = blockIdx.y * 128;

    float acc[4][8][4];
#pragma unroll
    for (int i = 0; i < 4; i++)
#pragma unroll
        for (int j = 0; j < 8; j++)
#pragma unroll
            for (int k = 0; k < 4; k++) acc[i][j][k] = 0.f;

    // prologue: 3 stages in flight
    load_stage(sb, 0, 0, m0, n0, tid); CP_COMMIT();
    load_stage(sb, 1, 1, m0, n0, tid); CP_COMMIT();
    load_stage(sb, 2, 2, m0, n0, tid); CP_COMMIT();

    // ldmatrix lane addressing (constant across stages)
    const int a_row  = lane & 15;
    const int a_col8 = (lane >> 4) & 1;            // +8 bf16 col
    const int b_n    = ((lane >> 4) & 1) * 8 + (lane & 7);
    const int b_k8   = (lane >> 3) & 1;            // +8 bf16 col

    for (int kb = 0; kb < NKB; kb++) {
        const int rem = NKB - 1 - kb;
        if (rem >= 2)      CP_WAIT(2);
        else if (rem == 1) CP_WAIT(1);
        else               CP_WAIT(0);
        __syncthreads();

        if (kb + 3 < NKB) {
            load_stage(sb, (kb + 3) & 3, kb + 3, m0, n0, tid);
            CP_COMMIT();
        }

        const uint32_t abase = sb + (kb & 3) * STAGEB;
        const uint32_t bbase = abase + ABYTES;
#pragma unroll
        for (int kh = 0; kh < 2; kh++) {
            uint32_t a[4][4], b[8][2];
            const int acol = kh * 16 + a_col8 * 8;
#pragma unroll
            for (int mt = 0; mt < 4; mt++) {
                const int r = wm * 64 + mt * 16 + a_row;
                LDMATRIX_X4(a[mt][0], a[mt][1], a[mt][2], a[mt][3],
                            abase + r * ROWB + acol * 2);
            }
            const int bcol = kh * 16 + b_k8 * 8;
#pragma unroll
            for (int np = 0; np < 4; np++) {
                const int n = wn * 64 + np * 16 + b_n;
                uint32_t r0, r1, r2, r3;
                LDMATRIX_X4(r0, r1, r2, r3, bbase + n * ROWB + bcol * 2);
                b[np * 2][0] = r0; b[np * 2][1] = r1;
                b[np * 2 + 1][0] = r2; b[np * 2 + 1][1] = r3;
            }
#pragma unroll
            for (int mt = 0; mt < 4; mt++)
#pragma unroll
                for (int nt = 0; nt < 8; nt++)
                    mma16816(acc[mt][nt], a[mt][0], a[mt][1], a[mt][2], a[mt][3],
                             b[nt][0], b[nt][1]);
        }
    }
    __syncthreads();   // SMEM now reusable for reduction

    // --------- fused epilogue: bias + row (max, sumexp) partials ------------
    float2 (*red)[2] = (float2(*)[2])(smem + OFF_RED);
#pragma unroll
    for (int mt = 0; mt < 4; mt++) {
#pragma unroll
        for (int half = 0; half < 2; half++) {
            const int rloc = wm * 64 + mt * 16 + g + half * 8;
            float v[16];
            float vmax = -1e30f;
#pragma unroll
            for (int nt = 0; nt < 8; nt++) {
                const int c0g = n0 + wn * 64 + nt * 8 + tig * 2;
                float v0 = acc[mt][nt][half * 2 + 0] + bias[c0g];
                float v1 = acc[mt][nt][half * 2 + 1] + bias[c0g + 1];
                v[nt * 2]     = v0;
                v[nt * 2 + 1] = v1;
                vmax = fmaxf(vmax, fmaxf(v0, v1));
            }
            float vsum = 0.f;
#pragma unroll
            for (int j = 0; j < 16; j++) vsum += __expf(v[j] - vmax);
#pragma unroll
            for (int off = 1; off < 4; off <<= 1) {
                float om = __shfl_xor_sync(0xffffffffu, vmax, off);
                float os = __shfl_xor_sync(0xffffffffu, vsum, off);
                float nm = fmaxf(vmax, om);
                vsum = vsum * __expf(vmax - nm) + os * __expf(om - nm);
                vmax = nm;
            }
            if (tig == 0) red[rloc][wn] = make_float2(vmax, vsum);
        }
    }
    __syncthreads();
    if (tid < 128) {
        float m = -1e30f, s = 0.f;
#pragma unroll
        for (int w = 0; w < 2; w++) {
            float2 p = red[tid][w];
            float nm = fmaxf(m, p.x);
            s = s * __expf(m - nm) + p.y * __expf(p.x - nm);
            m = nm;
        }
        const size_t idx = (size_t)(m0 + tid) * NP + blockIdx.y;
        g_pmax[idx] = m;
        g_psum[idx] = s;
    }
}

// ---------------- combine partials -> per-token logp ------------------------
__global__ void lse_kernel(const int* __restrict__ target) {
    const int row  = blockIdx.x * 8 + (threadIdx.x >> 5);
    const int lane = threadIdx.x & 31;
    const float* pm = g_pmax + (size_t)row * NP;
    const float* ps = g_psum + (size_t)row * NP;
    float m = -1e30f, s = 0.f;
    for (int j = lane; j < NP; j += 32) {
        float om = pm[j], os = ps[j];
        float nm = fmaxf(m, om);
        s = s * __expf(m - nm) + os * __expf(om - nm);
        m = nm;
    }
#pragma unroll
    for (int off = 16; off; off >>= 1) {
        float om = __shfl_xor_sync(0xffffffffu, m, off);
        float os = __shfl_xor_sync(0xffffffffu, s, off);
        float nm = fmaxf(m, om);
        s = s * __expf(m - nm) + os * __expf(om - nm);
        m = nm;
    }
    if (lane == 0) {
        const float lse = m + logf(s);
        const int t = target[row];
        g_ptok[row] = (t != IGNORE_INDEX) ? (g_tgt[row] - lse) : 0.f;
    }
}

// ---------------- final scalar loss -----------------------------------------
__global__ void final_kernel(const int* __restrict__ target,
                             const float* __restrict__ ref_c,
                             const float* __restrict__ ref_r,
                             float* __restrict__ out) {
    __shared__ float ssum[8];
    __shared__ float scnt[8];
    const int warp = threadIdx.x >> 5;
    const int lane = threadIdx.x & 31;
    float s = 0.f, c = 0.f;
    for (int t = lane; t < SEQ; t += 32) {
        const int row = warp * SEQ + t;
        if (target[row] != IGNORE_INDEX) {
            s += g_ptok[row];
            c += 1.f;
        }
    }
#pragma unroll
    for (int off = 16; off; off >>= 1) {
        s += __shfl_xor_sync(0xffffffffu, s, off);
        c += __shfl_xor_sync(0xffffffffu, c, off);
    }
    if (lane == 0) { ssum[warp] = s; scnt[warp] = c; }
    __syncthreads();
    if (threadIdx.x == 0) {
        float nll_num = 0.f, nll_den = 0.f;
        for (int b = 0; b < 4; b++) { nll_num += ssum[b]; nll_den += scnt[b]; }
        const float nll = -nll_num / nll_den;
        float pl = 0.f;
        for (int i = 0; i < 4; i++) {
            const float ca = ssum[i] / scnt[i] - ref_c[i];
            const float ra = ssum[4 + i] / scnt[4 + i] - ref_r[i];
            const float x  = 0.1f * (ca - ra);
            const float ls = fminf(x, 0.f) - log1pf(expf(-fabsf(x)));
            pl -= ls;
        }
        pl *= 0.25f;
        out[0] = pl + nll;
    }
}

// ---------------- launcher ---------------------------------------------------
extern "C" void kernel_launch(void* const* d_in, const int* in_sizes, int n_in,
                              void* d_out, int out_size) {
    const float* lin_w = (const float*)d_in[0];
    const float* x     = (const float*)d_in[1];
    const int*   tgt   = (const int*)d_in[2];
    const float* ref_c = (const float*)d_in[3];
    const float* ref_r = (const float*)d_in[4];
    const float* bias  = (const float*)d_in[5];
    float* out = (float*)d_out;

    cudaFuncSetAttribute(gemm_lse_kernel,
                         cudaFuncAttributeMaxDynamicSharedMemorySize, SMEM_BYTES);

    __nv_bfloat162* dW;
    __nv_bfloat162* dX;
    cudaGetSymbolAddress((void**)&dW, g_W);
    cudaGetSymbolAddress((void**)&dX, g_X);

    conv_kernel<<<2048, 256>>>((const float4*)lin_w, dW, VOCAB * HIDDEN / 4);
    conv_kernel<<<512, 256>>>((const float4*)x, dX, NTOK * HIDDEN / 4);

    tgt_kernel<<<NTOK / 8, 256>>>(x, lin_w, bias, tgt);

    dim3 grid(NTOK / 128, NP);   // m fast-varying -> B panel shared in-wave
    gemm_lse_kernel<<<grid, 128, SMEM_BYTES>>>(bias);

    lse_kernel<<<NTOK / 8, 256>>>(tgt);
    final_kernel<<<1, 256>>>(tgt, ref_c, ref_r, out);
}

// round 15
// speedup vs baseline: 1.4273x; 1.0076x over previous
#include <cuda_runtime.h>
#include <cuda_bf16.h>
#include <cstdint>

#define VOCAB  32000
#define HIDDEN 4096
#define NTOK   4096      // 8*512 tokens
#define SEQ    512
#define NP     250       // VOCAB / 128 partial tiles per row
#define IGNORE_INDEX (-100)

#define BK     32                // bf16 per K block
#define NKB    (HIDDEN / BK)     // 128
#define NSTAGE 4
#define ROWB   80                // padded row stride in bytes (40 bf16)
#define ABYTES (128 * ROWB)      // 10240 per operand per stage
#define STAGEB (2 * ABYTES)      // 20480 (A then B)
#define OFF_RED (NSTAGE * STAGEB)            // 81920
#define SMEM_BYTES (OFF_RED + 128 * 2 * 8)   // + red[128][2] float2 = 83968

// fused precursor kernel block ranges
#define PRE_W_BLOCKS 2048
#define PRE_X_BLOCKS 512
#define PRE_T_BLOCKS (NTOK / 8)   // 512
#define PRE_BLOCKS   (PRE_W_BLOCKS + PRE_X_BLOCKS + PRE_T_BLOCKS)

// ---------------- scratch (device globals; no allocation allowed) ----------
__device__ __align__(128) __nv_bfloat16 g_W[(size_t)VOCAB * HIDDEN];  // 262 MB
__device__ __align__(128) __nv_bfloat16 g_X[(size_t)NTOK * HIDDEN];   // 33 MB
__device__ float g_pmax[(size_t)NTOK * NP];
__device__ float g_psum[(size_t)NTOK * NP];
__device__ float g_tgt[NTOK];
__device__ float g_ptok[NTOK];

// ---------------- small asm helpers ----------------------------------------
__device__ __forceinline__ uint32_t smem_u32(const void* p) {
    uint32_t a;
    asm("{ .reg .u64 t; cvta.to.shared.u64 t, %1; cvt.u32.u64 %0, t; }"
        : "=r"(a) : "l"(p));
    return a;
}
#define CP_ASYNC16(dst, src) \
    asm volatile("cp.async.cg.shared.global [%0], [%1], 16;" :: "r"(dst), "l"(src))
#define CP_COMMIT() asm volatile("cp.async.commit_group;" ::: "memory")
#define CP_WAIT(n)  asm volatile("cp.async.wait_group %0;" :: "n"(n) : "memory")

#define LDMATRIX_X4(r0, r1, r2, r3, addr) \
    asm volatile("ldmatrix.sync.aligned.m8n8.x4.shared.b16 {%0,%1,%2,%3}, [%4];" \
                 : "=r"(r0), "=r"(r1), "=r"(r2), "=r"(r3) : "r"(addr))

__device__ __forceinline__ void mma16816(float c[4],
                                         uint32_t a0, uint32_t a1, uint32_t a2, uint32_t a3,
                                         uint32_t b0, uint32_t b1) {
    asm volatile(
        "mma.sync.aligned.m16n8k16.row.col.f32.bf16.bf16.f32 "
        "{%0,%1,%2,%3}, {%4,%5,%6,%7}, {%8,%9}, {%0,%1,%2,%3};\n"
        : "+f"(c[0]), "+f"(c[1]), "+f"(c[2]), "+f"(c[3])
        : "r"(a0), "r"(a1), "r"(a2), "r"(a3), "r"(b0), "r"(b1));
}

// ---------------- fused precursor: conv W | conv X | exact target logits ----
__global__ void pre_kernel(const float4* __restrict__ w4,
                           const float4* __restrict__ x4,
                           const float* __restrict__ x,
                           const float* __restrict__ w,
                           const float* __restrict__ bias,
                           const int* __restrict__ target) {
    const int b = blockIdx.x;
    if (b < PRE_W_BLOCKS) {
        // convert W: fp32 -> bf16
        __nv_bfloat162* dst = reinterpret_cast<__nv_bfloat162*>(g_W);
        const int n4 = VOCAB * HIDDEN / 4;
        for (int i = b * blockDim.x + threadIdx.x; i < n4;
             i += PRE_W_BLOCKS * blockDim.x) {
            float4 v = w4[i];
            dst[2 * i]     = __floats2bfloat162_rn(v.x, v.y);
            dst[2 * i + 1] = __floats2bfloat162_rn(v.z, v.w);
        }
    } else if (b < PRE_W_BLOCKS + PRE_X_BLOCKS) {
        // convert X: fp32 -> bf16
        __nv_bfloat162* dst = reinterpret_cast<__nv_bfloat162*>(g_X);
        const int bb = b - PRE_W_BLOCKS;
        const int n4 = NTOK * HIDDEN / 4;
        for (int i = bb * blockDim.x + threadIdx.x; i < n4;
             i += PRE_X_BLOCKS * blockDim.x) {
            float4 v = x4[i];
            dst[2 * i]     = __floats2bfloat162_rn(v.x, v.y);
            dst[2 * i + 1] = __floats2bfloat162_rn(v.z, v.w);
        }
    } else {
        // exact fp32 target logits: one warp per token row
        const int bb   = b - PRE_W_BLOCKS - PRE_X_BLOCKS;
        const int row  = bb * 8 + (threadIdx.x >> 5);
        const int lane = threadIdx.x & 31;
        const int t = target[row];
        if (t == IGNORE_INDEX) {
            if (lane == 0) g_tgt[row] = 0.f;
            return;
        }
        const float4* xr = reinterpret_cast<const float4*>(x + (size_t)row * HIDDEN);
        const float4* wr = reinterpret_cast<const float4*>(w + (size_t)t * HIDDEN);
        float s = 0.f;
#pragma unroll 4
        for (int j = lane; j < HIDDEN / 4; j += 32) {
            float4 a = xr[j];
            float4 bv = wr[j];
            s += a.x * bv.x + a.y * bv.y + a.z * bv.z + a.w * bv.w;
        }
#pragma unroll
        for (int off = 16; off; off >>= 1)
            s += __shfl_xor_sync(0xffffffffu, s, off);
        if (lane == 0) g_tgt[row] = s + bias[t];
    }
}

// ---------------- stage loader: cp.async GMEM bf16 -> padded SMEM -----------
// 128 threads: 512 16B chunks per operand per stage -> 4 per thread each.
__device__ __forceinline__ void load_stage(uint32_t sb, int stage, int kb,
                                           int m0, int n0, int tid) {
    const uint32_t base = sb + stage * STAGEB;
#pragma unroll
    for (int h = 0; h < 4; h++) {
        const int c   = tid + h * 128;
        const int row = c >> 2;
        const int seg = c & 3;
        const uint32_t dA = base + row * ROWB + seg * 16;
        const __nv_bfloat16* sA = g_X + (size_t)(m0 + row) * HIDDEN + kb * BK + seg * 8;
        CP_ASYNC16(dA, sA);
        const uint32_t dB = base + ABYTES + row * ROWB + seg * 16;
        const __nv_bfloat16* sB = g_W + (size_t)(n0 + row) * HIDDEN + kb * BK + seg * 8;
        CP_ASYNC16(dB, sB);
    }
}

// ---------------- bf16 GEMM (ldmatrix + mma.16816) + fused LSE --------------
// Grid (32 m-tiles [fast], 250 n-tiles). 128 threads, 4 warps (2x2).
// CTA tile 128x128, warp tile 64x64, BK=32, 4-stage cp.async pipeline.
__global__ __launch_bounds__(128, 2)
void gemm_lse_kernel(const float* __restrict__ bias) {
    extern __shared__ char smem[];
    const uint32_t sb = smem_u32(smem);

    const int tid  = threadIdx.x;
    const int lane = tid & 31;
    const int warp = tid >> 5;
    const int g    = lane >> 2;     // 0..7
    const int tig  = lane & 3;      // 0..3
    const int wm   = warp >> 1;     // 0..1 : rows wm*64..+63
    const int wn   = warp & 1;      // 0..1 : cols wn*64..+63
    const int m0   = blockIdx.x * 128;
    const int n0   = blockIdx.y * 128;

    float acc[4][8][4];
#pragma unroll
    for (int i = 0; i < 4; i++)
#pragma unroll
        for (int j = 0; j < 8; j++)
#pragma unroll
            for (int k = 0; k < 4; k++) acc[i][j][k] = 0.f;

    // prologue: 3 stages in flight
    load_stage(sb, 0, 0, m0, n0, tid); CP_COMMIT();
    load_stage(sb, 1, 1, m0, n0, tid); CP_COMMIT();
    load_stage(sb, 2, 2, m0, n0, tid); CP_COMMIT();

    // ldmatrix lane addressing (constant across stages)
    const int a_row  = lane & 15;
    const int a_col8 = (lane >> 4) & 1;            // +8 bf16 col
    const int b_n    = ((lane >> 4) & 1) * 8 + (lane & 7);
    const int b_k8   = (lane >> 3) & 1;            // +8 bf16 col

    for (int kb = 0; kb < NKB; kb++) {
        const int rem = NKB - 1 - kb;
        if (rem >= 2)      CP_WAIT(2);
        else if (rem == 1) CP_WAIT(1);
        else               CP_WAIT(0);
        __syncthreads();

        if (kb + 3 < NKB) {
            load_stage(sb, (kb + 3) & 3, kb + 3, m0, n0, tid);
            CP_COMMIT();
        }

        const uint32_t abase = sb + (kb & 3) * STAGEB;
        const uint32_t bbase = abase + ABYTES;
#pragma unroll
        for (int kh = 0; kh < 2; kh++) {
            uint32_t a[4][4], b[8][2];
            const int acol = kh * 16 + a_col8 * 8;
#pragma unroll
            for (int mt = 0; mt < 4; mt++) {
                const int r = wm * 64 + mt * 16 + a_row;
                LDMATRIX_X4(a[mt][0], a[mt][1], a[mt][2], a[mt][3],
                            abase + r * ROWB + acol * 2);
            }
            const int bcol = kh * 16 + b_k8 * 8;
#pragma unroll
            for (int np = 0; np < 4; np++) {
                const int n = wn * 64 + np * 16 + b_n;
                uint32_t r0, r1, r2, r3;
                LDMATRIX_X4(r0, r1, r2, r3, bbase + n * ROWB + bcol * 2);
                b[np * 2][0] = r0; b[np * 2][1] = r1;
                b[np * 2 + 1][0] = r2; b[np * 2 + 1][1] = r3;
            }
#pragma unroll
            for (int mt = 0; mt < 4; mt++)
#pragma unroll
                for (int nt = 0; nt < 8; nt++)
                    mma16816(acc[mt][nt], a[mt][0], a[mt][1], a[mt][2], a[mt][3],
                             b[nt][0], b[nt][1]);
        }
    }
    __syncthreads();   // SMEM now reusable for reduction

    // --------- fused epilogue: bias + row (max, sumexp) partials ------------
    float2 (*red)[2] = (float2(*)[2])(smem + OFF_RED);
#pragma unroll
    for (int mt = 0; mt < 4; mt++) {
#pragma unroll
        for (int half = 0; half < 2; half++) {
            const int rloc = wm * 64 + mt * 16 + g + half * 8;
            float v[16];
            float vmax = -1e30f;
#pragma unroll
            for (int nt = 0; nt < 8; nt++) {
                const int c0g = n0 + wn * 64 + nt * 8 + tig * 2;
                float v0 = acc[mt][nt][half * 2 + 0] + bias[c0g];
                float v1 = acc[mt][nt][half * 2 + 1] + bias[c0g + 1];
                v[nt * 2]     = v0;
                v[nt * 2 + 1] = v1;
                vmax = fmaxf(vmax, fmaxf(v0, v1));
            }
            float vsum = 0.f;
#pragma unroll
            for (int j = 0; j < 16; j++) vsum += __expf(v[j] - vmax);
#pragma unroll
            for (int off = 1; off < 4; off <<= 1) {
                float om = __shfl_xor_sync(0xffffffffu, vmax, off);
                float os = __shfl_xor_sync(0xffffffffu, vsum, off);
                float nm = fmaxf(vmax, om);
                vsum = vsum * __expf(vmax - nm) + os * __expf(om - nm);
                vmax = nm;
            }
            if (tig == 0) red[rloc][wn] = make_float2(vmax, vsum);
        }
    }
    __syncthreads();
    if (tid < 128) {
        float m = -1e30f, s = 0.f;
#pragma unroll
        for (int w = 0; w < 2; w++) {
            float2 p = red[tid][w];
            float nm = fmaxf(m, p.x);
            s = s * __expf(m - nm) + p.y * __expf(p.x - nm);
            m = nm;
        }
        const size_t idx = (size_t)(m0 + tid) * NP + blockIdx.y;
        g_pmax[idx] = m;
        g_psum[idx] = s;
    }
}

// ---------------- combine partials -> per-token logp ------------------------
__global__ void lse_kernel(const int* __restrict__ target) {
    const int row  = blockIdx.x * 8 + (threadIdx.x >> 5);
    const int lane = threadIdx.x & 31;
    const float* pm = g_pmax + (size_t)row * NP;
    const float* ps = g_psum + (size_t)row * NP;
    float m = -1e30f, s = 0.f;
    for (int j = lane; j < NP; j += 32) {
        float om = pm[j], os = ps[j];
        float nm = fmaxf(m, om);
        s = s * __expf(m - nm) + os * __expf(om - nm);
        m = nm;
    }
#pragma unroll
    for (int off = 16; off; off >>= 1) {
        float om = __shfl_xor_sync(0xffffffffu, m, off);
        float os = __shfl_xor_sync(0xffffffffu, s, off);
        float nm = fmaxf(m, om);
        s = s * __expf(m - nm) + os * __expf(om - nm);
        m = nm;
    }
    if (lane == 0) {
        const float lse = m + logf(s);
        const int t = target[row];
        g_ptok[row] = (t != IGNORE_INDEX) ? (g_tgt[row] - lse) : 0.f;
    }
}

// ---------------- final scalar loss -----------------------------------------
__global__ void final_kernel(const int* __restrict__ target,
                             const float* __restrict__ ref_c,
                             const float* __restrict__ ref_r,
                             float* __restrict__ out) {
    __shared__ float ssum[8];
    __shared__ float scnt[8];
    const int warp = threadIdx.x >> 5;
    const int lane = threadIdx.x & 31;
    float s = 0.f, c = 0.f;
    for (int t = lane; t < SEQ; t += 32) {
        const int row = warp * SEQ + t;
        if (target[row] != IGNORE_INDEX) {
            s += g_ptok[row];
            c += 1.f;
        }
    }
#pragma unroll
    for (int off = 16; off; off >>= 1) {
        s += __shfl_xor_sync(0xffffffffu, s, off);
        c += __shfl_xor_sync(0xffffffffu, c, off);
    }
    if (lane == 0) { ssum[warp] = s; scnt[warp] = c; }
    __syncthreads();
    if (threadIdx.x == 0) {
        float nll_num = 0.f, nll_den = 0.f;
        for (int b = 0; b < 4; b++) { nll_num += ssum[b]; nll_den += scnt[b]; }
        const float nll = -nll_num / nll_den;
        float pl = 0.f;
        for (int i = 0; i < 4; i++) {
            const float ca = ssum[i] / scnt[i] - ref_c[i];
            const float ra = ssum[4 + i] / scnt[4 + i] - ref_r[i];
            const float x  = 0.1f * (ca - ra);
            const float ls = fminf(x, 0.f) - log1pf(expf(-fabsf(x)));
            pl -= ls;
        }
        pl *= 0.25f;
        out[0] = pl + nll;
    }
}

// ---------------- launcher ---------------------------------------------------
extern "C" void kernel_launch(void* const* d_in, const int* in_sizes, int n_in,
                              void* d_out, int out_size) {
    const float* lin_w = (const float*)d_in[0];
    const float* x     = (const float*)d_in[1];
    const int*   tgt   = (const int*)d_in[2];
    const float* ref_c = (const float*)d_in[3];
    const float* ref_r = (const float*)d_in[4];
    const float* bias  = (const float*)d_in[5];
    float* out = (float*)d_out;

    cudaFuncSetAttribute(gemm_lse_kernel,
                         cudaFuncAttributeMaxDynamicSharedMemorySize, SMEM_BYTES);

    pre_kernel<<<PRE_BLOCKS, 256>>>((const float4*)lin_w, (const float4*)x,
                                    x, lin_w, bias, tgt);

    dim3 grid(NTOK / 128, NP);   // m fast-varying -> B panel shared in-wave
    gemm_lse_kernel<<<grid, 128, SMEM_BYTES>>>(bias);

    lse_kernel<<<NTOK / 8, 256>>>(tgt);
    final_kernel<<<1, 256>>>(tgt, ref_c, ref_r, out);
}

// round 16
// speedup vs baseline: 1.4330x; 1.0040x over previous
#include <cuda_runtime.h>
#include <cuda_bf16.h>
#include <cstdint>

#define VOCAB  32000
#define HIDDEN 4096
#define NTOK   4096      // 8*512 tokens
#define SEQ    512
#define NP     250       // VOCAB / 128 partial tiles per row
#define IGNORE_INDEX (-100)

#define BK     32                // bf16 per K block
#define NKB    (HIDDEN / BK)     // 128
#define NSTAGE 4
#define ROWB   80                // padded row stride in bytes (40 bf16)
#define ABYTES (128 * ROWB)      // 10240 per operand per stage
#define STAGEB (2 * ABYTES)      // 20480 (A then B)
#define OFF_RED (NSTAGE * STAGEB)            // 81920
#define SMEM_BYTES (OFF_RED + 128 * 2 * 8)   // + red[128][2] float2 = 83968

// fused precursor kernel block ranges
#define PRE_W_BLOCKS 2048
#define PRE_X_BLOCKS 512
#define PRE_T_BLOCKS (NTOK / 8)   // 512
#define PRE_BLOCKS   (PRE_W_BLOCKS + PRE_X_BLOCKS + PRE_T_BLOCKS)

#define NLSE (NTOK / 8)           // 512 lse blocks, 8 rows each (same batch)

// ---------------- scratch (device globals; no allocation allowed) ----------
__device__ __align__(128) __nv_bfloat16 g_W[(size_t)VOCAB * HIDDEN];  // 262 MB
__device__ __align__(128) __nv_bfloat16 g_X[(size_t)NTOK * HIDDEN];   // 33 MB
__device__ float g_pmax[(size_t)NTOK * NP];
__device__ float g_psum[(size_t)NTOK * NP];
__device__ float g_tgt[NTOK];
__device__ float2 g_part[NLSE];   // per-lse-block (sum_logp, valid_count)

// ---------------- small asm helpers ----------------------------------------
__device__ __forceinline__ uint32_t smem_u32(const void* p) {
    uint32_t a;
    asm("{ .reg .u64 t; cvta.to.shared.u64 t, %1; cvt.u32.u64 %0, t; }"
        : "=r"(a) : "l"(p));
    return a;
}
#define CP_ASYNC16(dst, src) \
    asm volatile("cp.async.cg.shared.global [%0], [%1], 16;" :: "r"(dst), "l"(src))
#define CP_COMMIT() asm volatile("cp.async.commit_group;" ::: "memory")
#define CP_WAIT(n)  asm volatile("cp.async.wait_group %0;" :: "n"(n) : "memory")

#define LDMATRIX_X4(r0, r1, r2, r3, addr) \
    asm volatile("ldmatrix.sync.aligned.m8n8.x4.shared.b16 {%0,%1,%2,%3}, [%4];" \
                 : "=r"(r0), "=r"(r1), "=r"(r2), "=r"(r3) : "r"(addr))

__device__ __forceinline__ void mma16816(float c[4],
                                         uint32_t a0, uint32_t a1, uint32_t a2, uint32_t a3,
                                         uint32_t b0, uint32_t b1) {
    asm volatile(
        "mma.sync.aligned.m16n8k16.row.col.f32.bf16.bf16.f32 "
        "{%0,%1,%2,%3}, {%4,%5,%6,%7}, {%8,%9}, {%0,%1,%2,%3};\n"
        : "+f"(c[0]), "+f"(c[1]), "+f"(c[2]), "+f"(c[3])
        : "r"(a0), "r"(a1), "r"(a2), "r"(a3), "r"(b0), "r"(b1));
}

// ---------------- fused precursor: conv W | conv X | exact target logits ----
__global__ void pre_kernel(const float4* __restrict__ w4,
                           const float4* __restrict__ x4,
                           const float* __restrict__ x,
                           const float* __restrict__ w,
                           const float* __restrict__ bias,
                           const int* __restrict__ target) {
    const int b = blockIdx.x;
    if (b < PRE_W_BLOCKS) {
        // convert W: fp32 -> bf16
        __nv_bfloat162* dst = reinterpret_cast<__nv_bfloat162*>(g_W);
        const int n4 = VOCAB * HIDDEN / 4;
        for (int i = b * blockDim.x + threadIdx.x; i < n4;
             i += PRE_W_BLOCKS * blockDim.x) {
            float4 v = w4[i];
            dst[2 * i]     = __floats2bfloat162_rn(v.x, v.y);
            dst[2 * i + 1] = __floats2bfloat162_rn(v.z, v.w);
        }
    } else if (b < PRE_W_BLOCKS + PRE_X_BLOCKS) {
        // convert X: fp32 -> bf16
        __nv_bfloat162* dst = reinterpret_cast<__nv_bfloat162*>(g_X);
        const int bb = b - PRE_W_BLOCKS;
        const int n4 = NTOK * HIDDEN / 4;
        for (int i = bb * blockDim.x + threadIdx.x; i < n4;
             i += PRE_X_BLOCKS * blockDim.x) {
            float4 v = x4[i];
            dst[2 * i]     = __floats2bfloat162_rn(v.x, v.y);
            dst[2 * i + 1] = __floats2bfloat162_rn(v.z, v.w);
        }
    } else {
        // exact fp32 target logits: one warp per token row
        const int bb   = b - PRE_W_BLOCKS - PRE_X_BLOCKS;
        const int row  = bb * 8 + (threadIdx.x >> 5);
        const int lane = threadIdx.x & 31;
        const int t = target[row];
        if (t == IGNORE_INDEX) {
            if (lane == 0) g_tgt[row] = 0.f;
            return;
        }
        const float4* xr = reinterpret_cast<const float4*>(x + (size_t)row * HIDDEN);
        const float4* wr = reinterpret_cast<const float4*>(w + (size_t)t * HIDDEN);
        float s = 0.f;
#pragma unroll 4
        for (int j = lane; j < HIDDEN / 4; j += 32) {
            float4 a = xr[j];
            float4 bv = wr[j];
            s += a.x * bv.x + a.y * bv.y + a.z * bv.z + a.w * bv.w;
        }
#pragma unroll
        for (int off = 16; off; off >>= 1)
            s += __shfl_xor_sync(0xffffffffu, s, off);
        if (lane == 0) g_tgt[row] = s + bias[t];
    }
}

// ---------------- stage loader: cp.async GMEM bf16 -> padded SMEM -----------
// 128 threads: 512 16B chunks per operand per stage -> 4 per thread each.
__device__ __forceinline__ void load_stage(uint32_t sb, int stage, int kb,
                                           int m0, int n0, int tid) {
    const uint32_t base = sb + stage * STAGEB;
#pragma unroll
    for (int h = 0; h < 4; h++) {
        const int c   = tid + h * 128;
        const int row = c >> 2;
        const int seg = c & 3;
        const uint32_t dA = base + row * ROWB + seg * 16;
        const __nv_bfloat16* sA = g_X + (size_t)(m0 + row) * HIDDEN + kb * BK + seg * 8;
        CP_ASYNC16(dA, sA);
        const uint32_t dB = base + ABYTES + row * ROWB + seg * 16;
        const __nv_bfloat16* sB = g_W + (size_t)(n0 + row) * HIDDEN + kb * BK + seg * 8;
        CP_ASYNC16(dB, sB);
    }
}

// ---------------- bf16 GEMM (ldmatrix + mma.16816) + fused LSE --------------
// Grid (32 m-tiles [fast], 250 n-tiles). 128 threads, 4 warps (2x2).
// CTA tile 128x128, warp tile 64x64, BK=32, 4-stage cp.async pipeline.
__global__ __launch_bounds__(128, 2)
void gemm_lse_kernel(const float* __restrict__ bias) {
    extern __shared__ char smem[];
    const uint32_t sb = smem_u32(smem);

    const int tid  = threadIdx.x;
    const int lane = tid & 31;
    const int warp = tid >> 5;
    const int g    = lane >> 2;     // 0..7
    const int tig  = lane & 3;      // 0..3
    const int wm   = warp >> 1;     // 0..1 : rows wm*64..+63
    const int wn   = warp & 1;      // 0..1 : cols wn*64..+63
    const int m0   = blockIdx.x * 128;
    const int n0   = blockIdx.y * 128;

    float acc[4][8][4];
#pragma unroll
    for (int i = 0; i < 4; i++)
#pragma unroll
        for (int j = 0; j < 8; j++)
#pragma unroll
            for (int k = 0; k < 4; k++) acc[i][j][k] = 0.f;

    // prologue: 3 stages in flight
    load_stage(sb, 0, 0, m0, n0, tid); CP_COMMIT();
    load_stage(sb, 1, 1, m0, n0, tid); CP_COMMIT();
    load_stage(sb, 2, 2, m0, n0, tid); CP_COMMIT();

    // ldmatrix lane addressing (constant across stages)
    const int a_row  = lane & 15;
    const int a_col8 = (lane >> 4) & 1;            // +8 bf16 col
    const int b_n    = ((lane >> 4) & 1) * 8 + (lane & 7);
    const int b_k8   = (lane >> 3) & 1;            // +8 bf16 col

    for (int kb = 0; kb < NKB; kb++) {
        const int rem = NKB - 1 - kb;
        if (rem >= 2)      CP_WAIT(2);
        else if (rem == 1) CP_WAIT(1);
        else               CP_WAIT(0);
        __syncthreads();

        if (kb + 3 < NKB) {
            load_stage(sb, (kb + 3) & 3, kb + 3, m0, n0, tid);
            CP_COMMIT();
        }

        const uint32_t abase = sb + (kb & 3) * STAGEB;
        const uint32_t bbase = abase + ABYTES;
#pragma unroll
        for (int kh = 0; kh < 2; kh++) {
            uint32_t a[4][4], b[8][2];
            const int acol = kh * 16 + a_col8 * 8;
#pragma unroll
            for (int mt = 0; mt < 4; mt++) {
                const int r = wm * 64 + mt * 16 + a_row;
                LDMATRIX_X4(a[mt][0], a[mt][1], a[mt][2], a[mt][3],
                            abase + r * ROWB + acol * 2);
            }
            const int bcol = kh * 16 + b_k8 * 8;
#pragma unroll
            for (int np = 0; np < 4; np++) {
                const int n = wn * 64 + np * 16 + b_n;
                uint32_t r0, r1, r2, r3;
                LDMATRIX_X4(r0, r1, r2, r3, bbase + n * ROWB + bcol * 2);
                b[np * 2][0] = r0; b[np * 2][1] = r1;
                b[np * 2 + 1][0] = r2; b[np * 2 + 1][1] = r3;
            }
#pragma unroll
            for (int mt = 0; mt < 4; mt++)
#pragma unroll
                for (int nt = 0; nt < 8; nt++)
                    mma16816(acc[mt][nt], a[mt][0], a[mt][1], a[mt][2], a[mt][3],
                             b[nt][0], b[nt][1]);
        }
    }
    __syncthreads();   // SMEM now reusable for reduction

    // --------- fused epilogue: bias + row (max, sumexp) partials ------------
    float2 (*red)[2] = (float2(*)[2])(smem + OFF_RED);
#pragma unroll
    for (int mt = 0; mt < 4; mt++) {
#pragma unroll
        for (int half = 0; half < 2; half++) {
            const int rloc = wm * 64 + mt * 16 + g + half * 8;
            float v[16];
            float vmax = -1e30f;
#pragma unroll
            for (int nt = 0; nt < 8; nt++) {
                const int c0g = n0 + wn * 64 + nt * 8 + tig * 2;
                float v0 = acc[mt][nt][half * 2 + 0] + bias[c0g];
                float v1 = acc[mt][nt][half * 2 + 1] + bias[c0g + 1];
                v[nt * 2]     = v0;
                v[nt * 2 + 1] = v1;
                vmax = fmaxf(vmax, fmaxf(v0, v1));
            }
            float vsum = 0.f;
#pragma unroll
            for (int j = 0; j < 16; j++) vsum += __expf(v[j] - vmax);
#pragma unroll
            for (int off = 1; off < 4; off <<= 1) {
                float om = __shfl_xor_sync(0xffffffffu, vmax, off);
                float os = __shfl_xor_sync(0xffffffffu, vsum, off);
                float nm = fmaxf(vmax, om);
                vsum = vsum * __expf(vmax - nm) + os * __expf(om - nm);
                vmax = nm;
            }
            if (tig == 0) red[rloc][wn] = make_float2(vmax, vsum);
        }
    }
    __syncthreads();
    if (tid < 128) {
        float m = -1e30f, s = 0.f;
#pragma unroll
        for (int w = 0; w < 2; w++) {
            float2 p = red[tid][w];
            float nm = fmaxf(m, p.x);
            s = s * __expf(m - nm) + p.y * __expf(p.x - nm);
            m = nm;
        }
        const size_t idx = (size_t)(m0 + tid) * NP + blockIdx.y;
        g_pmax[idx] = m;
        g_psum[idx] = s;
    }
}

// ---------------- combine partials -> per-block (sum_logp, count) -----------
__global__ void lse_kernel(const int* __restrict__ target) {
    __shared__ float2 sh[8];
    const int wid  = threadIdx.x >> 5;
    const int row  = blockIdx.x * 8 + wid;
    const int lane = threadIdx.x & 31;
    const float* pm = g_pmax + (size_t)row * NP;
    const float* ps = g_psum + (size_t)row * NP;
    float m = -1e30f, s = 0.f;
    for (int j = lane; j < NP; j += 32) {
        float om = pm[j], os = ps[j];
        float nm = fmaxf(m, om);
        s = s * __expf(m - nm) + os * __expf(om - nm);
        m = nm;
    }
#pragma unroll
    for (int off = 16; off; off >>= 1) {
        float om = __shfl_xor_sync(0xffffffffu, m, off);
        float os = __shfl_xor_sync(0xffffffffu, s, off);
        float nm = fmaxf(m, om);
        s = s * __expf(m - nm) + os * __expf(om - nm);
        m = nm;
    }
    if (lane == 0) {
        const float lse = m + logf(s);
        const int t = target[row];
        const bool valid = (t != IGNORE_INDEX);
        sh[wid] = make_float2(valid ? (g_tgt[row] - lse) : 0.f,
                              valid ? 1.f : 0.f);
    }
    __syncthreads();
    if (threadIdx.x == 0) {
        float ssum = 0.f, scnt = 0.f;
#pragma unroll
        for (int w = 0; w < 8; w++) { ssum += sh[w].x; scnt += sh[w].y; }
        g_part[blockIdx.x] = make_float2(ssum, scnt);
    }
}

// ---------------- final scalar loss (reads 512 float2 partials) -------------
__global__ void final_kernel(const float* __restrict__ ref_c,
                             const float* __restrict__ ref_r,
                             float* __restrict__ out) {
    __shared__ float ssum[8];
    __shared__ float scnt[8];
    const int warp = threadIdx.x >> 5;   // one warp per batch row
    const int lane = threadIdx.x & 31;
    const int nblk = NLSE / 8;           // 64 partials per batch
    float s = 0.f, c = 0.f;
#pragma unroll
    for (int h = 0; h < 2; h++) {
        float2 p = g_part[warp * nblk + lane + h * 32];
        s += p.x;
        c += p.y;
    }
#pragma unroll
    for (int off = 16; off; off >>= 1) {
        s += __shfl_xor_sync(0xffffffffu, s, off);
        c += __shfl_xor_sync(0xffffffffu, c, off);
    }
    if (lane == 0) { ssum[warp] = s; scnt[warp] = c; }
    __syncthreads();
    if (threadIdx.x == 0) {
        float nll_num = 0.f, nll_den = 0.f;
        for (int b = 0; b < 4; b++) { nll_num += ssum[b]; nll_den += scnt[b]; }
        const float nll = -nll_num / nll_den;
        float pl = 0.f;
        for (int i = 0; i < 4; i++) {
            const float ca = ssum[i] / scnt[i] - ref_c[i];
            const float ra = ssum[4 + i] / scnt[4 + i] - ref_r[i];
            const float x  = 0.1f * (ca - ra);
            const float ls = fminf(x, 0.f) - log1pf(expf(-fabsf(x)));
            pl -= ls;
        }
        pl *= 0.25f;
        out[0] = pl + nll;
    }
}

// ---------------- launcher ---------------------------------------------------
extern "C" void kernel_launch(void* const* d_in, const int* in_sizes, int n_in,
                              void* d_out, int out_size) {
    const float* lin_w = (const float*)d_in[0];
    const float* x     = (const float*)d_in[1];
    const int*   tgt   = (const int*)d_in[2];
    const float* ref_c = (const float*)d_in[3];
    const float* ref_r = (const float*)d_in[4];
    const float* bias  = (const float*)d_in[5];
    float* out = (float*)d_out;

    cudaFuncSetAttribute(gemm_lse_kernel,
                         cudaFuncAttributeMaxDynamicSharedMemorySize, SMEM_BYTES);

    pre_kernel<<<PRE_BLOCKS, 256>>>((const float4*)lin_w, (const float4*)x,
                                    x, lin_w, bias, tgt);

    dim3 grid(NTOK / 128, NP);   // m fast-varying -> B panel shared in-wave
    gemm_lse_kernel<<<grid, 128, SMEM_BYTES>>>(bias);

    lse_kernel<<<NLSE, 256>>>(tgt);
    final_kernel<<<1, 256>>>(ref_c, ref_r, out);
}

// round 17
// speedup vs baseline: 1.4337x; 1.0005x over previous
#include <cuda_runtime.h>
#include <cuda_bf16.h>
#include <cstdint>

#define VOCAB  32000
#define HIDDEN 4096
#define NTOK   4096      // 8*512 tokens
#define SEQ    512
#define NP     250       // VOCAB / 128 partial tiles per row
#define IGNORE_INDEX (-100)

#define BK     32                // bf16 per K block
#define NKB    (HIDDEN / BK)     // 128
#define NSTAGE 4
#define ROWB   80                // padded row stride in bytes (40 bf16)
#define ABYTES (128 * ROWB)      // 10240 per operand per stage
#define STAGEB (2 * ABYTES)      // 20480 (A then B)
#define OFF_RED (NSTAGE * STAGEB)            // 81920
#define SMEM_BYTES (OFF_RED + 128 * 2 * 8)   // + red[128][2] float2 = 83968

// fused precursor kernel block ranges
#define PRE_W_BLOCKS 2048
#define PRE_X_BLOCKS 512
#define PRE_T_BLOCKS (NTOK / 8)   // 512
#define PRE_BLOCKS   (PRE_W_BLOCKS + PRE_X_BLOCKS + PRE_T_BLOCKS)

#define NLSE (NTOK / 8)           // 512 lse blocks, 8 rows each (same batch)

// ---------------- scratch (device globals; no allocation allowed) ----------
__device__ __align__(128) __nv_bfloat16 g_W[(size_t)VOCAB * HIDDEN];  // 262 MB
__device__ __align__(128) __nv_bfloat16 g_X[(size_t)NTOK * HIDDEN];   // 33 MB
__device__ float g_pmax[(size_t)NTOK * NP];
__device__ float g_psum[(size_t)NTOK * NP];
__device__ float g_tgt[NTOK];
__device__ float2 g_part[NLSE];   // per-lse-block (sum_logp, valid_count)
__device__ unsigned int g_ctr;    // zero-initialized; reset by last block

// ---------------- small asm helpers ----------------------------------------
__device__ __forceinline__ uint32_t smem_u32(const void* p) {
    uint32_t a;
    asm("{ .reg .u64 t; cvta.to.shared.u64 t, %1; cvt.u32.u64 %0, t; }"
        : "=r"(a) : "l"(p));
    return a;
}
#define CP_ASYNC16(dst, src) \
    asm volatile("cp.async.cg.shared.global [%0], [%1], 16;" :: "r"(dst), "l"(src))
#define CP_COMMIT() asm volatile("cp.async.commit_group;" ::: "memory")
#define CP_WAIT(n)  asm volatile("cp.async.wait_group %0;" :: "n"(n) : "memory")

#define LDMATRIX_X4(r0, r1, r2, r3, addr) \
    asm volatile("ldmatrix.sync.aligned.m8n8.x4.shared.b16 {%0,%1,%2,%3}, [%4];" \
                 : "=r"(r0), "=r"(r1), "=r"(r2), "=r"(r3) : "r"(addr))

__device__ __forceinline__ void mma16816(float c[4],
                                         uint32_t a0, uint32_t a1, uint32_t a2, uint32_t a3,
                                         uint32_t b0, uint32_t b1) {
    asm volatile(
        "mma.sync.aligned.m16n8k16.row.col.f32.bf16.bf16.f32 "
        "{%0,%1,%2,%3}, {%4,%5,%6,%7}, {%8,%9}, {%0,%1,%2,%3};\n"
        : "+f"(c[0]), "+f"(c[1]), "+f"(c[2]), "+f"(c[3])
        : "r"(a0), "r"(a1), "r"(a2), "r"(a3), "r"(b0), "r"(b1));
}

// ---------------- fused precursor: conv W | conv X | exact target logits ----
__global__ void pre_kernel(const float4* __restrict__ w4,
                           const float4* __restrict__ x4,
                           const float* __restrict__ x,
                           const float* __restrict__ w,
                           const float* __restrict__ bias,
                           const int* __restrict__ target) {
    const int b = blockIdx.x;
    if (b < PRE_W_BLOCKS) {
        // convert W: fp32 -> bf16
        __nv_bfloat162* dst = reinterpret_cast<__nv_bfloat162*>(g_W);
        const int n4 = VOCAB * HIDDEN / 4;
        for (int i = b * blockDim.x + threadIdx.x; i < n4;
             i += PRE_W_BLOCKS * blockDim.x) {
            float4 v = w4[i];
            dst[2 * i]     = __floats2bfloat162_rn(v.x, v.y);
            dst[2 * i + 1] = __floats2bfloat162_rn(v.z, v.w);
        }
    } else if (b < PRE_W_BLOCKS + PRE_X_BLOCKS) {
        // convert X: fp32 -> bf16
        __nv_bfloat162* dst = reinterpret_cast<__nv_bfloat162*>(g_X);
        const int bb = b - PRE_W_BLOCKS;
        const int n4 = NTOK * HIDDEN / 4;
        for (int i = bb * blockDim.x + threadIdx.x; i < n4;
             i += PRE_X_BLOCKS * blockDim.x) {
            float4 v = x4[i];
            dst[2 * i]     = __floats2bfloat162_rn(v.x, v.y);
            dst[2 * i + 1] = __floats2bfloat162_rn(v.z, v.w);
        }
    } else {
        // exact fp32 target logits: one warp per token row
        const int bb   = b - PRE_W_BLOCKS - PRE_X_BLOCKS;
        const int row  = bb * 8 + (threadIdx.x >> 5);
        const int lane = threadIdx.x & 31;
        const int t = target[row];
        if (t == IGNORE_INDEX) {
            if (lane == 0) g_tgt[row] = 0.f;
            return;
        }
        const float4* xr = reinterpret_cast<const float4*>(x + (size_t)row * HIDDEN);
        const float4* wr = reinterpret_cast<const float4*>(w + (size_t)t * HIDDEN);
        float s = 0.f;
#pragma unroll 4
        for (int j = lane; j < HIDDEN / 4; j += 32) {
            float4 a = xr[j];
            float4 bv = wr[j];
            s += a.x * bv.x + a.y * bv.y + a.z * bv.z + a.w * bv.w;
        }
#pragma unroll
        for (int off = 16; off; off >>= 1)
            s += __shfl_xor_sync(0xffffffffu, s, off);
        if (lane == 0) g_tgt[row] = s + bias[t];
    }
}

// ---------------- stage loader: cp.async GMEM bf16 -> padded SMEM -----------
// 128 threads: 512 16B chunks per operand per stage -> 4 per thread each.
__device__ __forceinline__ void load_stage(uint32_t sb, int stage, int kb,
                                           int m0, int n0, int tid) {
    const uint32_t base = sb + stage * STAGEB;
#pragma unroll
    for (int h = 0; h < 4; h++) {
        const int c   = tid + h * 128;
        const int row = c >> 2;
        const int seg = c & 3;
        const uint32_t dA = base + row * ROWB + seg * 16;
        const __nv_bfloat16* sA = g_X + (size_t)(m0 + row) * HIDDEN + kb * BK + seg * 8;
        CP_ASYNC16(dA, sA);
        const uint32_t dB = base + ABYTES + row * ROWB + seg * 16;
        const __nv_bfloat16* sB = g_W + (size_t)(n0 + row) * HIDDEN + kb * BK + seg * 8;
        CP_ASYNC16(dB, sB);
    }
}

// ---------------- bf16 GEMM (ldmatrix + mma.16816) + fused LSE --------------
// Grid (32 m-tiles [fast], 250 n-tiles). 128 threads, 4 warps (2x2).
// CTA tile 128x128, warp tile 64x64, BK=32, 4-stage cp.async pipeline.
__global__ __launch_bounds__(128, 2)
void gemm_lse_kernel(const float* __restrict__ bias) {
    extern __shared__ char smem[];
    const uint32_t sb = smem_u32(smem);

    const int tid  = threadIdx.x;
    const int lane = tid & 31;
    const int warp = tid >> 5;
    const int g    = lane >> 2;     // 0..7
    const int tig  = lane & 3;      // 0..3
    const int wm   = warp >> 1;     // 0..1 : rows wm*64..+63
    const int wn   = warp & 1;      // 0..1 : cols wn*64..+63
    const int m0   = blockIdx.x * 128;
    const int n0   = blockIdx.y * 128;

    float acc[4][8][4];
#pragma unroll
    for (int i = 0; i < 4; i++)
#pragma unroll
        for (int j = 0; j < 8; j++)
#pragma unroll
            for (int k = 0; k < 4; k++) acc[i][j][k] = 0.f;

    // prologue: 3 stages in flight
    load_stage(sb, 0, 0, m0, n0, tid); CP_COMMIT();
    load_stage(sb, 1, 1, m0, n0, tid); CP_COMMIT();
    load_stage(sb, 2, 2, m0, n0, tid); CP_COMMIT();

    // ldmatrix lane addressing (constant across stages)
    const int a_row  = lane & 15;
    const int a_col8 = (lane >> 4) & 1;            // +8 bf16 col
    const int b_n    = ((lane >> 4) & 1) * 8 + (lane & 7);
    const int b_k8   = (lane >> 3) & 1;            // +8 bf16 col

    for (int kb = 0; kb < NKB; kb++) {
        const int rem = NKB - 1 - kb;
        if (rem >= 2)      CP_WAIT(2);
        else if (rem == 1) CP_WAIT(1);
        else               CP_WAIT(0);
        __syncthreads();

        if (kb + 3 < NKB) {
            load_stage(sb, (kb + 3) & 3, kb + 3, m0, n0, tid);
            CP_COMMIT();
        }

        const uint32_t abase = sb + (kb & 3) * STAGEB;
        const uint32_t bbase = abase + ABYTES;
#pragma unroll
        for (int kh = 0; kh < 2; kh++) {
            uint32_t a[4][4], b[8][2];
            const int acol = kh * 16 + a_col8 * 8;
#pragma unroll
            for (int mt = 0; mt < 4; mt++) {
                const int r = wm * 64 + mt * 16 + a_row;
                LDMATRIX_X4(a[mt][0], a[mt][1], a[mt][2], a[mt][3],
                            abase + r * ROWB + acol * 2);
            }
            const int bcol = kh * 16 + b_k8 * 8;
#pragma unroll
            for (int np = 0; np < 4; np++) {
                const int n = wn * 64 + np * 16 + b_n;
                uint32_t r0, r1, r2, r3;
                LDMATRIX_X4(r0, r1, r2, r3, bbase + n * ROWB + bcol * 2);
                b[np * 2][0] = r0; b[np * 2][1] = r1;
                b[np * 2 + 1][0] = r2; b[np * 2 + 1][1] = r3;
            }
#pragma unroll
            for (int mt = 0; mt < 4; mt++)
#pragma unroll
                for (int nt = 0; nt < 8; nt++)
                    mma16816(acc[mt][nt], a[mt][0], a[mt][1], a[mt][2], a[mt][3],
                             b[nt][0], b[nt][1]);
        }
    }
    __syncthreads();   // SMEM now reusable for reduction

    // --------- fused epilogue: bias + row (max, sumexp) partials ------------
    float2 (*red)[2] = (float2(*)[2])(smem + OFF_RED);
#pragma unroll
    for (int mt = 0; mt < 4; mt++) {
#pragma unroll
        for (int half = 0; half < 2; half++) {
            const int rloc = wm * 64 + mt * 16 + g + half * 8;
            float v[16];
            float vmax = -1e30f;
#pragma unroll
            for (int nt = 0; nt < 8; nt++) {
                const int c0g = n0 + wn * 64 + nt * 8 + tig * 2;
                float v0 = acc[mt][nt][half * 2 + 0] + bias[c0g];
                float v1 = acc[mt][nt][half * 2 + 1] + bias[c0g + 1];
                v[nt * 2]     = v0;
                v[nt * 2 + 1] = v1;
                vmax = fmaxf(vmax, fmaxf(v0, v1));
            }
            float vsum = 0.f;
#pragma unroll
            for (int j = 0; j < 16; j++) vsum += __expf(v[j] - vmax);
#pragma unroll
            for (int off = 1; off < 4; off <<= 1) {
                float om = __shfl_xor_sync(0xffffffffu, vmax, off);
                float os = __shfl_xor_sync(0xffffffffu, vsum, off);
                float nm = fmaxf(vmax, om);
                vsum = vsum * __expf(vmax - nm) + os * __expf(om - nm);
                vmax = nm;
            }
            if (tig == 0) red[rloc][wn] = make_float2(vmax, vsum);
        }
    }
    __syncthreads();
    if (tid < 128) {
        float m = -1e30f, s = 0.f;
#pragma unroll
        for (int w = 0; w < 2; w++) {
            float2 p = red[tid][w];
            float nm = fmaxf(m, p.x);
            s = s * __expf(m - nm) + p.y * __expf(p.x - nm);
            m = nm;
        }
        const size_t idx = (size_t)(m0 + tid) * NP + blockIdx.y;
        g_pmax[idx] = m;
        g_psum[idx] = s;
    }
}

// ------- combine partials -> per-block (sum, count); last block -> loss -----
__global__ void lse_kernel(const int* __restrict__ target,
                           const float* __restrict__ ref_c,
                           const float* __restrict__ ref_r,
                           float* __restrict__ out) {
    __shared__ float2 sh[8];
    __shared__ unsigned int s_last;
    const int wid  = threadIdx.x >> 5;
    const int row  = blockIdx.x * 8 + wid;
    const int lane = threadIdx.x & 31;
    const float* pm = g_pmax + (size_t)row * NP;
    const float* ps = g_psum + (size_t)row * NP;
    float m = -1e30f, s = 0.f;
    for (int j = lane; j < NP; j += 32) {
        float om = pm[j], os = ps[j];
        float nm = fmaxf(m, om);
        s = s * __expf(m - nm) + os * __expf(om - nm);
        m = nm;
    }
#pragma unroll
    for (int off = 16; off; off >>= 1) {
        float om = __shfl_xor_sync(0xffffffffu, m, off);
        float os = __shfl_xor_sync(0xffffffffu, s, off);
        float nm = fmaxf(m, om);
        s = s * __expf(m - nm) + os * __expf(om - nm);
        m = nm;
    }
    if (lane == 0) {
        const float lse = m + logf(s);
        const int t = target[row];
        const bool valid = (t != IGNORE_INDEX);
        sh[wid] = make_float2(valid ? (g_tgt[row] - lse) : 0.f,
                              valid ? 1.f : 0.f);
    }
    __syncthreads();
    if (threadIdx.x == 0) {
        float ssum = 0.f, scnt = 0.f;
#pragma unroll
        for (int w = 0; w < 8; w++) { ssum += sh[w].x; scnt += sh[w].y; }
        g_part[blockIdx.x] = make_float2(ssum, scnt);
        __threadfence();
        s_last = atomicAdd(&g_ctr, 1u);   // NLSE-1 for exactly one block
    }
    __syncthreads();
    if (s_last != NLSE - 1) return;

    // ---- last arriving block: final scalar loss (deterministic order) ------
    __threadfence();                      // acquire: all g_part writes visible
    __shared__ float fsum[8];
    __shared__ float fcnt[8];
    const int nblk = NLSE / 8;            // 64 partials per batch
    float fs = 0.f, fc = 0.f;
#pragma unroll
    for (int h = 0; h < 2; h++) {
        float2 p = g_part[wid * nblk + lane + h * 32];
        fs += p.x;
        fc += p.y;
    }
#pragma unroll
    for (int off = 16; off; off >>= 1) {
        fs += __shfl_xor_sync(0xffffffffu, fs, off);
        fc += __shfl_xor_sync(0xffffffffu, fc, off);
    }
    if (lane == 0) { fsum[wid] = fs; fcnt[wid] = fc; }
    __syncthreads();
    if (threadIdx.x == 0) {
        float nll_num = 0.f, nll_den = 0.f;
        for (int b = 0; b < 4; b++) { nll_num += fsum[b]; nll_den += fcnt[b]; }
        const float nll = -nll_num / nll_den;
        float pl = 0.f;
        for (int i = 0; i < 4; i++) {
            const float ca = fsum[i] / fcnt[i] - ref_c[i];
            const float ra = fsum[4 + i] / fcnt[4 + i] - ref_r[i];
            const float xx = 0.1f * (ca - ra);
            const float ls = fminf(xx, 0.f) - log1pf(expf(-fabsf(xx)));
            pl -= ls;
        }
        pl *= 0.25f;
        out[0] = pl + nll;
        g_ctr = 0;                         // reset for next graph replay
    }
}

// ---------------- launcher ---------------------------------------------------
extern "C" void kernel_launch(void* const* d_in, const int* in_sizes, int n_in,
                              void* d_out, int out_size) {
    const float* lin_w = (const float*)d_in[0];
    const float* x     = (const float*)d_in[1];
    const int*   tgt   = (const int*)d_in[2];
    const float* ref_c = (const float*)d_in[3];
    const float* ref_r = (const float*)d_in[4];
    const float* bias  = (const float*)d_in[5];
    float* out = (float*)d_out;

    cudaFuncSetAttribute(gemm_lse_kernel,
                         cudaFuncAttributeMaxDynamicSharedMemorySize, SMEM_BYTES);

    pre_kernel<<<PRE_BLOCKS, 256>>>((const float4*)lin_w, (const float4*)x,
                                    x, lin_w, bias, tgt);

    dim3 grid(NTOK / 128, NP);   // m fast-varying -> B panel shared in-wave
    gemm_lse_kernel<<<grid, 128, SMEM_BYTES>>>(bias);

    lse_kernel<<<NLSE, 256>>>(tgt, ref_c, ref_r, out);
}